// round 5
// baseline (speedup 1.0000x reference)
#include <cuda_runtime.h>
#include <cuda_bf16.h>

// Problem constants
#define BB   32
#define CC   512
#define NN   1024          // H*W = 32*32
#define CQ   64
#define MR   640           // Cq + Cq + C  (rows of concatenated weight)

// ---------------- scratch (no cudaMalloc allowed) ----------------
__device__ float g_scale[3];                     // 1/sigma for q,k,v
__device__ float g_wcat[MR * CC];                // scaled concatenated weights [640][512]
__device__ float g_bcat[MR];                     // concatenated bias
__device__ float g_qkv[BB * MR * NN];            // per batch: rows 0..63 q, 64..127 k, 128..639 v  (all [chan][n])
__device__ float g_p[(size_t)BB * NN * NN];      // exp(qk)  [b][n_query][m_key]
__device__ float g_cinv[BB * NN];                // 1 / colsum

// =================================================================
// Spectral norm: sigma = || W * normalize(W^T u) ||   (forward value)
// one block per weight, 512 threads
// =================================================================
__global__ void spectral_k(const float* __restrict__ Wq, const float* __restrict__ uq,
                           const float* __restrict__ Wk, const float* __restrict__ uk,
                           const float* __restrict__ Wv, const float* __restrict__ uv) {
    const float* W; const float* u; int out;
    if (blockIdx.x == 0)      { W = Wq; u = uq; out = CQ; }
    else if (blockIdx.x == 1) { W = Wk; u = uk; out = CQ; }
    else                      { W = Wv; u = uv; out = CC; }
    const int in = CC;

    __shared__ float sv[CC];
    __shared__ float st[CC];
    __shared__ float red[16];

    int tid  = threadIdx.x;           // 512 threads
    int lane = tid & 31, w = tid >> 5;

    // v[j] = sum_i W[i][j] * u[i]   (coalesced: thread j reads column j)
    float acc = 0.f;
    for (int i = 0; i < out; i++) acc += W[i * in + tid] * u[i];
    sv[tid] = acc;

    // ||v||
    float s = acc * acc;
    #pragma unroll
    for (int o = 16; o; o >>= 1) s += __shfl_xor_sync(0xffffffffu, s, o);
    if (lane == 0) red[w] = s;
    __syncthreads();
    if (tid < 16) {
        float r = red[tid];
        #pragma unroll
        for (int o = 8; o; o >>= 1) r += __shfl_xor_sync(0xffffu, r, o);
        if (tid == 0) red[0] = r;
    }
    __syncthreads();
    float inv = rsqrtf(red[0]);       // 1/||v||
    __syncthreads();                  // everyone has read red[0]

    // t[i] = (W v)[i], one warp per row group (coalesced within warp)
    for (int i = w; i < out; i += 16) {
        float a = 0.f;
        for (int j = lane; j < in; j += 32) a += W[i * in + j] * sv[j];
        #pragma unroll
        for (int o = 16; o; o >>= 1) a += __shfl_xor_sync(0xffffffffu, a, o);
        if (lane == 0) st[i] = a * inv;
    }
    __syncthreads();

    // sigma^2 = sum t^2
    float q = (tid < out) ? st[tid] * st[tid] : 0.f;
    #pragma unroll
    for (int o = 16; o; o >>= 1) q += __shfl_xor_sync(0xffffffffu, q, o);
    if (lane == 0) red[w] = q;
    __syncthreads();
    if (tid == 0) {
        float r = 0.f;
        #pragma unroll
        for (int i = 0; i < 16; i++) r += red[i];
        g_scale[blockIdx.x] = rsqrtf(r);      // 1/sigma
    }
}

// =================================================================
// Build scaled concatenated weight [640][512] and bias [640]
// =================================================================
__global__ void build_wcat(const float* __restrict__ Wq, const float* __restrict__ bq,
                           const float* __restrict__ Wk, const float* __restrict__ bk,
                           const float* __restrict__ Wv, const float* __restrict__ bv) {
    int idx = blockIdx.x * blockDim.x + threadIdx.x;    // 640*512
    if (idx >= MR * CC) return;
    int r = idx >> 9, c = idx & (CC - 1);
    float wv, sc;
    if (r < CQ)            { wv = Wq[r * CC + c];          sc = g_scale[0]; }
    else if (r < 2 * CQ)   { wv = Wk[(r - CQ) * CC + c];   sc = g_scale[1]; }
    else                   { wv = Wv[(r - 2*CQ) * CC + c]; sc = g_scale[2]; }
    g_wcat[idx] = wv * sc;
    if (c == 0)
        g_bcat[r] = (r < CQ) ? bq[r] : (r < 2*CQ ? bk[r - CQ] : bv[r - 2*CQ]);
}

// =================================================================
// GEMM 1: qkv[b][r][n] = wcat[r][:] . x[b][:][n] + bcat[r]
// A row-major [M=640][K=512], B row-major [K=512][N=1024]
// 128x128 tile, BK=8, 256 threads, 8x8/thread (stride-16 interleave)
// =================================================================
__global__ __launch_bounds__(256, 2)
void gemm_proj(const float* __restrict__ x) {
    int b  = blockIdx.z;
    int m0 = blockIdx.y * 128;
    int n0 = blockIdx.x * 128;
    const float* A  = g_wcat;
    const float* Bm = x + (size_t)b * CC * NN;

    __shared__ float As[8][132];   // padded: transposed store conflict-free
    __shared__ float Bs[8][128];

    float acc[8][8];
    #pragma unroll
    for (int i = 0; i < 8; i++)
        #pragma unroll
        for (int j = 0; j < 8; j++) acc[i][j] = 0.f;

    int tid = threadIdx.x;
    int tx = tid & 15, ty = tid >> 4;
    int a_m = tid >> 3, a_k = tid & 7;     // A tile: 32 rows/pass x 4
    int b_k = tid >> 5, b_n = tid & 31;    // B tile: 8 rows, 32 cols/pass x 4

    float ra[4], rb[4];
    #pragma unroll
    for (int i = 0; i < 4; i++) ra[i] = A[(m0 + a_m + 32*i) * CC + a_k];
    #pragma unroll
    for (int i = 0; i < 4; i++) rb[i] = Bm[b_k * NN + n0 + b_n + 32*i];

    const int KT = CC / 8;
    for (int kt = 0; kt < KT; kt++) {
        __syncthreads();
        #pragma unroll
        for (int i = 0; i < 4; i++) As[a_k][a_m + 32*i] = ra[i];
        #pragma unroll
        for (int i = 0; i < 4; i++) Bs[b_k][b_n + 32*i] = rb[i];
        __syncthreads();
        if (kt + 1 < KT) {
            int k0 = (kt + 1) * 8;
            #pragma unroll
            for (int i = 0; i < 4; i++) ra[i] = A[(m0 + a_m + 32*i) * CC + k0 + a_k];
            #pragma unroll
            for (int i = 0; i < 4; i++) rb[i] = Bm[(k0 + b_k) * NN + n0 + b_n + 32*i];
        }
        #pragma unroll
        for (int kk = 0; kk < 8; kk++) {
            float af[8], bf[8];
            #pragma unroll
            for (int i = 0; i < 8; i++) af[i] = As[kk][ty + 16*i];
            #pragma unroll
            for (int j = 0; j < 8; j++) bf[j] = Bs[kk][tx + 16*j];
            #pragma unroll
            for (int i = 0; i < 8; i++)
                #pragma unroll
                for (int j = 0; j < 8; j++) acc[i][j] += af[i] * bf[j];
        }
    }

    float* Cp = g_qkv + (size_t)b * MR * NN;
    #pragma unroll
    for (int i = 0; i < 8; i++) {
        int r = m0 + ty + 16*i;
        float bias = g_bcat[r];
        #pragma unroll
        for (int j = 0; j < 8; j++)
            Cp[r * NN + n0 + tx + 16*j] = acc[i][j] + bias;
    }
}

// =================================================================
// GEMM 2: p[b][n][m] = exp( sum_o q[b][o][n] * k[b][o][m] )
// Both operands are [K=64][1024] channel-major -> direct (no transpose) loads
// =================================================================
__global__ __launch_bounds__(256, 2)
void gemm_qk(void) {
    int b  = blockIdx.z;
    int m0 = blockIdx.y * 128;   // query-n block
    int n0 = blockIdx.x * 128;   // key-m block
    const float* Aq = g_qkv + (size_t)b * MR * NN;            // q: rows 0..63
    const float* Bk = g_qkv + (size_t)b * MR * NN + CQ * NN;  // k: rows 64..127

    __shared__ float As[8][128];
    __shared__ float Bs[8][128];

    float acc[8][8];
    #pragma unroll
    for (int i = 0; i < 8; i++)
        #pragma unroll
        for (int j = 0; j < 8; j++) acc[i][j] = 0.f;

    int tid = threadIdx.x;
    int tx = tid & 15, ty = tid >> 4;
    int l_k = tid >> 5, l_c = tid & 31;

    float ra[4], rb[4];
    #pragma unroll
    for (int i = 0; i < 4; i++) ra[i] = Aq[l_k * NN + m0 + l_c + 32*i];
    #pragma unroll
    for (int i = 0; i < 4; i++) rb[i] = Bk[l_k * NN + n0 + l_c + 32*i];

    const int KT = CQ / 8;    // 8
    for (int kt = 0; kt < KT; kt++) {
        __syncthreads();
        #pragma unroll
        for (int i = 0; i < 4; i++) As[l_k][l_c + 32*i] = ra[i];
        #pragma unroll
        for (int i = 0; i < 4; i++) Bs[l_k][l_c + 32*i] = rb[i];
        __syncthreads();
        if (kt + 1 < KT) {
            int k0 = (kt + 1) * 8;
            #pragma unroll
            for (int i = 0; i < 4; i++) ra[i] = Aq[(k0 + l_k) * NN + m0 + l_c + 32*i];
            #pragma unroll
            for (int i = 0; i < 4; i++) rb[i] = Bk[(k0 + l_k) * NN + n0 + l_c + 32*i];
        }
        #pragma unroll
        for (int kk = 0; kk < 8; kk++) {
            float af[8], bf[8];
            #pragma unroll
            for (int i = 0; i < 8; i++) af[i] = As[kk][ty + 16*i];
            #pragma unroll
            for (int j = 0; j < 8; j++) bf[j] = Bs[kk][tx + 16*j];
            #pragma unroll
            for (int i = 0; i < 8; i++)
                #pragma unroll
                for (int j = 0; j < 8; j++) acc[i][j] += af[i] * bf[j];
        }
    }

    float* Pp = g_p + (size_t)b * NN * NN;
    #pragma unroll
    for (int i = 0; i < 8; i++) {
        int nq = m0 + ty + 16*i;
        #pragma unroll
        for (int j = 0; j < 8; j++)
            Pp[(size_t)nq * NN + n0 + tx + 16*j] = __expf(acc[i][j]);
    }
}

// =================================================================
// Column sums (over query axis n) -> inverse
// grid (32 batches, 32 m-chunks), 256 threads: 8 n-slices x 32 cols
// =================================================================
__global__ void colsum_k(void) {
    int b  = blockIdx.x;
    int m0 = blockIdx.y * 32;
    int ml = threadIdx.x & 31;
    int ns = threadIdx.x >> 5;   // 0..7
    const float* p = g_p + (size_t)b * NN * NN + m0;
    float s0 = 0.f, s1 = 0.f;
    for (int n = ns; n < NN; n += 16) {
        s0 += p[(size_t)n * NN + ml];
        s1 += p[(size_t)(n + 8) * NN + ml];
    }
    __shared__ float part[8][32];
    part[ns][ml] = s0 + s1;
    __syncthreads();
    if (threadIdx.x < 32) {
        float t = 0.f;
        #pragma unroll
        for (int i = 0; i < 8; i++) t += part[i][threadIdx.x];
        g_cinv[b * NN + m0 + threadIdx.x] = 1.0f / t;
    }
}

// =================================================================
// GEMM 3: out[b][c][m] = gamma * (sum_n v[b][c][n] p[b][n][m]) * cinv[b][m] + x[b][c][m]
// A = v row-major [512][1024], B = p [1024][1024]
// =================================================================
__global__ __launch_bounds__(256, 2)
void gemm_av(const float* __restrict__ x, const float* __restrict__ gamma,
             float* __restrict__ out) {
    int b  = blockIdx.z;
    int m0 = blockIdx.y * 128;   // channel block
    int n0 = blockIdx.x * 128;   // spatial block
    const float* A  = g_qkv + (size_t)b * MR * NN + 2 * CQ * NN;  // v rows
    const float* Bm = g_p + (size_t)b * NN * NN;

    __shared__ float As[8][132];
    __shared__ float Bs[8][128];

    float acc[8][8];
    #pragma unroll
    for (int i = 0; i < 8; i++)
        #pragma unroll
        for (int j = 0; j < 8; j++) acc[i][j] = 0.f;

    int tid = threadIdx.x;
    int tx = tid & 15, ty = tid >> 4;
    int a_m = tid >> 3, a_k = tid & 7;
    int b_k = tid >> 5, b_n = tid & 31;

    float ra[4], rb[4];
    #pragma unroll
    for (int i = 0; i < 4; i++) ra[i] = A[(m0 + a_m + 32*i) * NN + a_k];
    #pragma unroll
    for (int i = 0; i < 4; i++) rb[i] = Bm[(size_t)b_k * NN + n0 + b_n + 32*i];

    const int KT = NN / 8;   // 128
    for (int kt = 0; kt < KT; kt++) {
        __syncthreads();
        #pragma unroll
        for (int i = 0; i < 4; i++) As[a_k][a_m + 32*i] = ra[i];
        #pragma unroll
        for (int i = 0; i < 4; i++) Bs[b_k][b_n + 32*i] = rb[i];
        __syncthreads();
        if (kt + 1 < KT) {
            int k0 = (kt + 1) * 8;
            #pragma unroll
            for (int i = 0; i < 4; i++) ra[i] = A[(m0 + a_m + 32*i) * NN + k0 + a_k];
            #pragma unroll
            for (int i = 0; i < 4; i++) rb[i] = Bm[(size_t)(k0 + b_k) * NN + n0 + b_n + 32*i];
        }
        #pragma unroll
        for (int kk = 0; kk < 8; kk++) {
            float af[8], bf[8];
            #pragma unroll
            for (int i = 0; i < 8; i++) af[i] = As[kk][ty + 16*i];
            #pragma unroll
            for (int j = 0; j < 8; j++) bf[j] = Bs[kk][tx + 16*j];
            #pragma unroll
            for (int i = 0; i < 8; i++)
                #pragma unroll
                for (int j = 0; j < 8; j++) acc[i][j] += af[i] * bf[j];
        }
    }

    float gm = *gamma;
    float scl[8];
    #pragma unroll
    for (int j = 0; j < 8; j++) scl[j] = gm * g_cinv[b * NN + n0 + tx + 16*j];

    #pragma unroll
    for (int i = 0; i < 8; i++) {
        int c = m0 + ty + 16*i;
        size_t rowo = (size_t)b * CC * NN + (size_t)c * NN;
        #pragma unroll
        for (int j = 0; j < 8; j++) {
            size_t o = rowo + n0 + tx + 16*j;
            out[o] = scl[j] * acc[i][j] + x[o];
        }
    }
}

// =================================================================
extern "C" void kernel_launch(void* const* d_in, const int* in_sizes, int n_in,
                              void* d_out, int out_size) {
    const float* x     = (const float*)d_in[0];
    const float* Wq    = (const float*)d_in[1];
    const float* bq    = (const float*)d_in[2];
    const float* uq    = (const float*)d_in[3];
    const float* Wk    = (const float*)d_in[4];
    const float* bk    = (const float*)d_in[5];
    const float* uk    = (const float*)d_in[6];
    const float* Wv    = (const float*)d_in[7];
    const float* bv    = (const float*)d_in[8];
    const float* uv    = (const float*)d_in[9];
    const float* gamma = (const float*)d_in[10];
    float* out = (float*)d_out;

    spectral_k<<<3, 512>>>(Wq, uq, Wk, uk, Wv, uv);
    build_wcat<<<(MR * CC + 255) / 256, 256>>>(Wq, bq, Wk, bk, Wv, bv);
    gemm_proj<<<dim3(NN/128, MR/128, BB), 256>>>(x);
    gemm_qk<<<dim3(NN/128, NN/128, BB), 256>>>();
    colsum_k<<<dim3(BB, NN/32), 256>>>();
    gemm_av<<<dim3(NN/128, CC/128, BB), 256>>>(x, gamma, out);
}

// round 7
// speedup vs baseline: 2.2134x; 2.2134x over previous
#include <cuda_runtime.h>
#include <cuda_bf16.h>
#include <cstdint>

#define BB 32
#define CC 512
#define NN 1024
#define CQ 64
#define MR 640

// ---------------- scratch (device globals; no cudaMalloc) ----------------
__device__ float g_scale[3];
__device__ float g_bcat[MR];
__device__ __align__(16) __nv_bfloat16 g_w2h[MR * CC];
__device__ __align__(16) __nv_bfloat16 g_w2l[MR * CC];
__device__ __align__(16) __nv_bfloat16 g_xTh[(size_t)BB * NN * CC];
__device__ __align__(16) __nv_bfloat16 g_xTl[(size_t)BB * NN * CC];
__device__ __align__(16) __nv_bfloat16 g_qTh[(size_t)BB * NN * CQ];
__device__ __align__(16) __nv_bfloat16 g_qTl[(size_t)BB * NN * CQ];
__device__ __align__(16) __nv_bfloat16 g_kTh[(size_t)BB * NN * CQ];
__device__ __align__(16) __nv_bfloat16 g_kTl[(size_t)BB * NN * CQ];
__device__ __align__(16) __nv_bfloat16 g_vh [(size_t)BB * CC * NN];
__device__ __align__(16) __nv_bfloat16 g_vl [(size_t)BB * CC * NN];
__device__ __align__(16) __nv_bfloat16 g_pTh[(size_t)BB * NN * NN];
__device__ __align__(16) __nv_bfloat16 g_pTl[(size_t)BB * NN * NN];
__device__ float g_cinv[BB * NN];

// ---------------- helpers ----------------
__device__ __forceinline__ uint32_t smem_u32(const void* p) {
    uint32_t a;
    asm("{ .reg .u64 t; cvta.to.shared.u64 t, %1; cvt.u32.u64 %0, t; }" : "=r"(a) : "l"(p));
    return a;
}
__device__ __forceinline__ void cp16(uint32_t s, const void* g) {
    asm volatile("cp.async.cg.shared.global [%0], [%1], 16;" :: "r"(s), "l"(g));
}
__device__ __forceinline__ void cp_commit() { asm volatile("cp.async.commit_group;" ::: "memory"); }
__device__ __forceinline__ void cp_wait1()  { asm volatile("cp.async.wait_group 1;" ::: "memory"); }
__device__ __forceinline__ void cp_wait0()  { asm volatile("cp.async.wait_group 0;" ::: "memory"); }

__device__ __forceinline__ void mma16816(float* c, uint32_t a0, uint32_t a1, uint32_t a2, uint32_t a3,
                                         uint32_t b0, uint32_t b1) {
    asm volatile(
        "mma.sync.aligned.m16n8k16.row.col.f32.bf16.bf16.f32 "
        "{%0,%1,%2,%3}, {%4,%5,%6,%7}, {%8,%9}, {%0,%1,%2,%3};"
        : "+f"(c[0]), "+f"(c[1]), "+f"(c[2]), "+f"(c[3])
        : "r"(a0), "r"(a1), "r"(a2), "r"(a3), "r"(b0), "r"(b1));
}

__device__ __forceinline__ void split2(float f, __nv_bfloat16& h, __nv_bfloat16& l) {
    h = __float2bfloat16(f);
    l = __float2bfloat16(f - __bfloat162float(h));
}
__device__ __forceinline__ uint32_t packbf(__nv_bfloat16 a, __nv_bfloat16 b) {
    __nv_bfloat162 t(a, b);
    return *reinterpret_cast<uint32_t*>(&t);
}

// smem geometry: per stage 4 arrays (Ah,Al,Bh,Bl), each 128 rows x 32 bf16
// stored with stride 40 elems (80 B) -> conflict-free fragment loads.
#define ARR_B   10240u
#define STAGE_B 40960u
#define SMEM_GEMM (2 * STAGE_B)          // 81920 B

// Issue one K-chunk (32 elems) of all 4 operand arrays into `stage` via cp.async.
__device__ __forceinline__ void issue_chunk(uint32_t su, int stage,
        const __nv_bfloat16* Ah, const __nv_bfloat16* Al, int lda,
        const __nv_bfloat16* Bh, const __nv_bfloat16* Bl, int ldb,
        int koff, int tid) {
    const __nv_bfloat16* ps[4] = { Ah, Al, Bh, Bl };
    #pragma unroll
    for (int a = 0; a < 4; a++) {
        int ld = (a < 2) ? lda : ldb;
        uint32_t sb = su + (uint32_t)stage * STAGE_B + (uint32_t)a * ARR_B;
        #pragma unroll
        for (int i = 0; i < 2; i++) {
            int idx = tid + 256 * i;
            int row = idx >> 2, seg = idx & 3;
            cp16(sb + (uint32_t)(row * 80 + seg * 16),
                 ps[a] + (size_t)row * ld + koff + seg * 8);
        }
    }
    cp_commit();
}

// One K-chunk of MMAs (2 ksteps x 4x4 tiles x 3 passes).
__device__ __forceinline__ void compute_chunk(const char* sm, int stage,
        int wm, int wn, int lane, float acc[4][4][4]) {
    int g = lane >> 2, t = lane & 3;
    const char* A0 = sm + stage * STAGE_B + (wm * 64 + g) * 80 + t * 4;
    const char* B0 = sm + stage * STAGE_B + 2 * ARR_B + (wn * 32 + g) * 80 + t * 4;
    #pragma unroll
    for (int kk = 0; kk < 2; kk++) {
        int kb = kk * 32;
        uint32_t ah[4][4], al[4][4], bh[4][2], bl[4][2];
        #pragma unroll
        for (int mt = 0; mt < 4; mt++) {
            const char* p = A0 + mt * 1280 + kb;
            ah[mt][0] = *(const uint32_t*)(p);
            ah[mt][1] = *(const uint32_t*)(p + 640);
            ah[mt][2] = *(const uint32_t*)(p + 16);
            ah[mt][3] = *(const uint32_t*)(p + 656);
            const char* q = p + ARR_B;
            al[mt][0] = *(const uint32_t*)(q);
            al[mt][1] = *(const uint32_t*)(q + 640);
            al[mt][2] = *(const uint32_t*)(q + 16);
            al[mt][3] = *(const uint32_t*)(q + 656);
        }
        #pragma unroll
        for (int nt = 0; nt < 4; nt++) {
            const char* p = B0 + nt * 640 + kb;
            bh[nt][0] = *(const uint32_t*)(p);
            bh[nt][1] = *(const uint32_t*)(p + 16);
            const char* q = p + ARR_B;
            bl[nt][0] = *(const uint32_t*)(q);
            bl[nt][1] = *(const uint32_t*)(q + 16);
        }
        #pragma unroll
        for (int mt = 0; mt < 4; mt++)
            #pragma unroll
            for (int nt = 0; nt < 4; nt++) {
                mma16816(acc[mt][nt], ah[mt][0], ah[mt][1], ah[mt][2], ah[mt][3], bh[nt][0], bh[nt][1]);
                mma16816(acc[mt][nt], al[mt][0], al[mt][1], al[mt][2], al[mt][3], bh[nt][0], bh[nt][1]);
                mma16816(acc[mt][nt], ah[mt][0], ah[mt][1], ah[mt][2], ah[mt][3], bl[nt][0], bl[nt][1]);
            }
    }
}

// Full double-buffered mainloop. acc indexed [mt][nt][4].
__device__ __forceinline__ void run_gemm(char* sm, uint32_t su,
        const __nv_bfloat16* Ah, const __nv_bfloat16* Al, int lda,
        const __nv_bfloat16* Bh, const __nv_bfloat16* Bl, int ldb,
        int nch, float acc[4][4][4]) {
    int tid = threadIdx.x, lane = tid & 31, wid = tid >> 5;
    int wm = wid >> 2, wn = wid & 3;
    #pragma unroll
    for (int i = 0; i < 4; i++)
        #pragma unroll
        for (int j = 0; j < 4; j++)
            #pragma unroll
            for (int e = 0; e < 4; e++) acc[i][j][e] = 0.f;

    issue_chunk(su, 0, Ah, Al, lda, Bh, Bl, ldb, 0, tid);
    issue_chunk(su, 1, Ah, Al, lda, Bh, Bl, ldb, 32, tid);
    for (int ch = 0; ch < nch; ch++) {
        if (ch == nch - 1) cp_wait0(); else cp_wait1();
        __syncthreads();
        compute_chunk(sm, ch & 1, wm, wn, lane, acc);
        __syncthreads();
        if (ch + 2 < nch)
            issue_chunk(su, ch & 1, Ah, Al, lda, Bh, Bl, ldb, (ch + 2) * 32, tid);
    }
}

// Stage one 64-row half of the 128x128 fp32 result into smem (stride 132).
__device__ __forceinline__ void stage_half(float* fb, int h, float acc[4][4][4]) {
    int tid = threadIdx.x, lane = tid & 31, wid = tid >> 5;
    int wm = wid >> 2, wn = wid & 3;
    if (wm != h) return;
    int g = lane >> 2, t = lane & 3;
    #pragma unroll
    for (int mt = 0; mt < 4; mt++)
        #pragma unroll
        for (int nt = 0; nt < 4; nt++) {
            float* p = fb + (mt * 16 + g) * 132 + wn * 32 + nt * 8 + 2 * t;
            p[0] = acc[mt][nt][0]; p[1] = acc[mt][nt][1];
            p[8 * 132] = acc[mt][nt][2]; p[8 * 132 + 1] = acc[mt][nt][3];
        }
}

// =================================================================
// Spectral norm (fp32)
// =================================================================
__global__ void spectral_k(const float* __restrict__ Wq, const float* __restrict__ uq,
                           const float* __restrict__ Wk, const float* __restrict__ uk,
                           const float* __restrict__ Wv, const float* __restrict__ uv) {
    const float* W; const float* u; int out;
    if (blockIdx.x == 0)      { W = Wq; u = uq; out = CQ; }
    else if (blockIdx.x == 1) { W = Wk; u = uk; out = CQ; }
    else                      { W = Wv; u = uv; out = CC; }
    const int in = CC;
    __shared__ float sv[CC];
    __shared__ float st[CC];
    __shared__ float red[16];
    int tid = threadIdx.x, lane = tid & 31, w = tid >> 5;

    float acc = 0.f;
    for (int i = 0; i < out; i++) acc += W[i * in + tid] * u[i];
    sv[tid] = acc;

    float s = acc * acc;
    #pragma unroll
    for (int o = 16; o; o >>= 1) s += __shfl_xor_sync(0xffffffffu, s, o);
    if (lane == 0) red[w] = s;
    __syncthreads();
    if (tid < 16) {
        float r = red[tid];
        #pragma unroll
        for (int o = 8; o; o >>= 1) r += __shfl_xor_sync(0xffffu, r, o);
        if (tid == 0) red[0] = r;
    }
    __syncthreads();
    float inv = rsqrtf(red[0]);
    __syncthreads();

    for (int i = w; i < out; i += 16) {
        float a = 0.f;
        for (int j = lane; j < in; j += 32) a += W[i * in + j] * sv[j];
        #pragma unroll
        for (int o = 16; o; o >>= 1) a += __shfl_xor_sync(0xffffffffu, a, o);
        if (lane == 0) st[i] = a * inv;
    }
    __syncthreads();

    float q = (tid < out) ? st[tid] * st[tid] : 0.f;
    #pragma unroll
    for (int o = 16; o; o >>= 1) q += __shfl_xor_sync(0xffffffffu, q, o);
    if (lane == 0) red[w] = q;
    __syncthreads();
    if (tid == 0) {
        float r = 0.f;
        #pragma unroll
        for (int i = 0; i < 16; i++) r += red[i];
        g_scale[blockIdx.x] = rsqrtf(r);
    }
}

// =================================================================
// Scaled concatenated weights -> bf16 hi/lo + fp32 bias
// =================================================================
__global__ void build_w2k(const float* __restrict__ Wq, const float* __restrict__ bq,
                          const float* __restrict__ Wk, const float* __restrict__ bk,
                          const float* __restrict__ Wv, const float* __restrict__ bv) {
    int idx = blockIdx.x * blockDim.x + threadIdx.x;
    if (idx >= MR * CC) return;
    int r = idx >> 9, c = idx & (CC - 1);
    float wv, sc;
    if (r < CQ)          { wv = Wq[r * CC + c];            sc = g_scale[0]; }
    else if (r < 2 * CQ) { wv = Wk[(r - CQ) * CC + c];     sc = g_scale[1]; }
    else                 { wv = Wv[(r - 2 * CQ) * CC + c]; sc = g_scale[2]; }
    __nv_bfloat16 h, l;
    split2(wv * sc, h, l);
    g_w2h[idx] = h; g_w2l[idx] = l;
    if (c == 0)
        g_bcat[r] = (r < CQ) ? bq[r] : (r < 2 * CQ ? bk[r - CQ] : bv[r - 2 * CQ]);
}

// =================================================================
// Transpose+split x: [b][c][n] fp32 -> xT hi/lo bf16 [b][n][c]
// =================================================================
__global__ void xsplit_k(const float* __restrict__ x) {
    __shared__ float t[32][33];
    int b = blockIdx.z, n0 = blockIdx.x * 32, c0 = blockIdx.y * 32;
    int tx = threadIdx.x, ty = threadIdx.y;   // 32 x 8
    const float* xb = x + (size_t)b * CC * NN;
    #pragma unroll
    for (int j = 0; j < 4; j++)
        t[ty + 8 * j][tx] = xb[(size_t)(c0 + ty + 8 * j) * NN + n0 + tx];
    __syncthreads();
    #pragma unroll
    for (int j = 0; j < 4; j++) {
        int n = n0 + ty + 8 * j;
        __nv_bfloat16 h, l;
        split2(t[tx][ty + 8 * j], h, l);
        size_t o = ((size_t)b * NN + n) * CC + c0 + tx;
        g_xTh[o] = h; g_xTl[o] = l;
    }
}

// =================================================================
// proj_qk: D[n][r] = xT[n][:]·w[r][:] + b[r]; rows n, cols r in [0,128)
// -> qT/kT hi/lo [b][n][64]
// =================================================================
__global__ __launch_bounds__(256)
void proj_qk_mma(void) {
    extern __shared__ __align__(16) char sm[];
    uint32_t su = smem_u32(sm);
    int b = blockIdx.z, n0 = blockIdx.x * 128;
    const __nv_bfloat16* Ah = g_xTh + ((size_t)b * NN + n0) * CC;
    const __nv_bfloat16* Al = g_xTl + ((size_t)b * NN + n0) * CC;
    float acc[4][4][4];
    run_gemm(sm, su, Ah, Al, CC, g_w2h, g_w2l, CC, CC / 32, acc);

    float* fb = (float*)sm;
    int tid = threadIdx.x, lane = tid & 31;
    for (int h = 0; h < 2; h++) {
        __syncthreads();
        stage_half(fb, h, acc);
        __syncthreads();
        #pragma unroll
        for (int j = 0; j < 8; j++) {
            int r = (tid >> 5) + j * 8;
            int n = n0 + h * 64 + r;
            int rr = lane * 4;
            const float* p = fb + r * 132 + rr;
            uint32_t hp[2], lp[2];
            #pragma unroll
            for (int e = 0; e < 2; e++) {
                float f0 = p[2 * e]     + g_bcat[rr + 2 * e];
                float f1 = p[2 * e + 1] + g_bcat[rr + 2 * e + 1];
                __nv_bfloat16 h0, l0, h1, l1;
                split2(f0, h0, l0); split2(f1, h1, l1);
                hp[e] = packbf(h0, h1); lp[e] = packbf(l0, l1);
            }
            size_t o;
            __nv_bfloat16 *dh, *dl;
            if (rr < 64) { o = ((size_t)b * NN + n) * CQ + rr;      dh = g_qTh; dl = g_qTl; }
            else         { o = ((size_t)b * NN + n) * CQ + rr - 64; dh = g_kTh; dl = g_kTl; }
            *reinterpret_cast<uint2*>(dh + o) = *reinterpret_cast<uint2*>(hp);
            *reinterpret_cast<uint2*>(dl + o) = *reinterpret_cast<uint2*>(lp);
        }
    }
}

// =================================================================
// proj_v: D[c][n] = wv[c][:]·xT[n][:] + bv[c] -> v hi/lo [b][c][n]
// =================================================================
__global__ __launch_bounds__(256)
void proj_v_mma(void) {
    extern __shared__ __align__(16) char sm[];
    uint32_t su = smem_u32(sm);
    int b = blockIdx.z, n0 = blockIdx.x * 128, c0 = blockIdx.y * 128;
    const __nv_bfloat16* Ah = g_w2h + (size_t)(2 * CQ + c0) * CC;
    const __nv_bfloat16* Al = g_w2l + (size_t)(2 * CQ + c0) * CC;
    const __nv_bfloat16* Bh = g_xTh + ((size_t)b * NN + n0) * CC;
    const __nv_bfloat16* Bl = g_xTl + ((size_t)b * NN + n0) * CC;
    float acc[4][4][4];
    run_gemm(sm, su, Ah, Al, CC, Bh, Bl, CC, CC / 32, acc);

    float* fb = (float*)sm;
    int tid = threadIdx.x, lane = tid & 31;
    for (int h = 0; h < 2; h++) {
        __syncthreads();
        stage_half(fb, h, acc);
        __syncthreads();
        #pragma unroll
        for (int j = 0; j < 8; j++) {
            int r = (tid >> 5) + j * 8;
            int c = c0 + h * 64 + r;
            float bias = g_bcat[2 * CQ + c];
            const float* p = fb + r * 132 + lane * 4;
            uint32_t hp[2], lp[2];
            #pragma unroll
            for (int e = 0; e < 2; e++) {
                __nv_bfloat16 h0, l0, h1, l1;
                split2(p[2 * e] + bias, h0, l0);
                split2(p[2 * e + 1] + bias, h1, l1);
                hp[e] = packbf(h0, h1); lp[e] = packbf(l0, l1);
            }
            size_t o = ((size_t)b * CC + c) * NN + n0 + lane * 4;
            *reinterpret_cast<uint2*>(g_vh + o) = *reinterpret_cast<uint2*>(hp);
            *reinterpret_cast<uint2*>(g_vl + o) = *reinterpret_cast<uint2*>(lp);
        }
    }
}

// =================================================================
// QK: D[m][n] = kT[m][:]·qT[n][:];  pT = exp(D) hi/lo [b][m][n]
// =================================================================
__global__ __launch_bounds__(256)
void gemm_qk_mma(void) {
    extern __shared__ __align__(16) char sm[];
    uint32_t su = smem_u32(sm);
    int b = blockIdx.z, m0 = blockIdx.y * 128, n0 = blockIdx.x * 128;
    const __nv_bfloat16* Ah = g_kTh + ((size_t)b * NN + m0) * CQ;
    const __nv_bfloat16* Al = g_kTl + ((size_t)b * NN + m0) * CQ;
    const __nv_bfloat16* Bh = g_qTh + ((size_t)b * NN + n0) * CQ;
    const __nv_bfloat16* Bl = g_qTl + ((size_t)b * NN + n0) * CQ;
    float acc[4][4][4];
    run_gemm(sm, su, Ah, Al, CQ, Bh, Bl, CQ, CQ / 32, acc);

    float* fb = (float*)sm;
    int tid = threadIdx.x, lane = tid & 31;
    for (int h = 0; h < 2; h++) {
        __syncthreads();
        stage_half(fb, h, acc);
        __syncthreads();
        #pragma unroll
        for (int j = 0; j < 8; j++) {
            int r = (tid >> 5) + j * 8;
            int m = m0 + h * 64 + r;
            const float* p = fb + r * 132 + lane * 4;
            uint32_t hp[2], lp[2];
            #pragma unroll
            for (int e = 0; e < 2; e++) {
                float f0 = __expf(p[2 * e]);
                float f1 = __expf(p[2 * e + 1]);
                __nv_bfloat16 h0, l0, h1, l1;
                split2(f0, h0, l0); split2(f1, h1, l1);
                hp[e] = packbf(h0, h1); lp[e] = packbf(l0, l1);
            }
            size_t o = ((size_t)b * NN + m) * NN + n0 + lane * 4;
            *reinterpret_cast<uint2*>(g_pTh + o) = *reinterpret_cast<uint2*>(hp);
            *reinterpret_cast<uint2*>(g_pTl + o) = *reinterpret_cast<uint2*>(lp);
        }
    }
}

// =================================================================
// colsum: cinv[b][m] = 1 / sum_n (pTh+pTl)[b][m][n]   (coalesced rows)
// =================================================================
__global__ void colsum_tc(void) {
    int gw = blockIdx.x * 8 + (threadIdx.x >> 5);
    int lane = threadIdx.x & 31;
    const __nv_bfloat162* ph = reinterpret_cast<const __nv_bfloat162*>(g_pTh) + (size_t)gw * (NN / 2);
    const __nv_bfloat162* pl = reinterpret_cast<const __nv_bfloat162*>(g_pTl) + (size_t)gw * (NN / 2);
    float s = 0.f;
    #pragma unroll
    for (int it = 0; it < 16; it++) {
        float2 a = __bfloat1622float2(ph[lane + 32 * it]);
        float2 c = __bfloat1622float2(pl[lane + 32 * it]);
        s += (a.x + c.x) + (a.y + c.y);
    }
    #pragma unroll
    for (int o = 16; o; o >>= 1) s += __shfl_xor_sync(0xffffffffu, s, o);
    if (lane == 0) g_cinv[gw] = 1.0f / s;
}

// =================================================================
// AV: D[c][m] = v[c][:]·pT[m][:];  out = gamma*cinv[m]*D + x
// =================================================================
__global__ __launch_bounds__(256)
void gemm_av_mma(const float* __restrict__ x, const float* __restrict__ gamma,
                 float* __restrict__ out) {
    extern __shared__ __align__(16) char sm[];
    uint32_t su = smem_u32(sm);
    int b = blockIdx.z, m0 = blockIdx.x * 128, c0 = blockIdx.y * 128;
    const __nv_bfloat16* Ah = g_vh  + ((size_t)b * CC + c0) * NN;
    const __nv_bfloat16* Al = g_vl  + ((size_t)b * CC + c0) * NN;
    const __nv_bfloat16* Bh = g_pTh + ((size_t)b * NN + m0) * NN;
    const __nv_bfloat16* Bl = g_pTl + ((size_t)b * NN + m0) * NN;
    float acc[4][4][4];
    run_gemm(sm, su, Ah, Al, NN, Bh, Bl, NN, NN / 32, acc);

    float* fb = (float*)sm;
    int tid = threadIdx.x, lane = tid & 31;
    float gm = *gamma;
    for (int h = 0; h < 2; h++) {
        __syncthreads();
        stage_half(fb, h, acc);
        __syncthreads();
        #pragma unroll
        for (int j = 0; j < 8; j++) {
            int r = (tid >> 5) + j * 8;
            int c = c0 + h * 64 + r;
            int m = m0 + lane * 4;
            float4 d = *reinterpret_cast<const float4*>(fb + r * 132 + lane * 4);
            float4 ci = *reinterpret_cast<const float4*>(g_cinv + b * NN + m);
            size_t o = ((size_t)b * CC + c) * NN + m;
            float4 xv = *reinterpret_cast<const float4*>(x + o);
            float4 ov;
            ov.x = gm * ci.x * d.x + xv.x;
            ov.y = gm * ci.y * d.y + xv.y;
            ov.z = gm * ci.z * d.z + xv.z;
            ov.w = gm * ci.w * d.w + xv.w;
            *reinterpret_cast<float4*>(out + o) = ov;
        }
    }
}

// =================================================================
extern "C" void kernel_launch(void* const* d_in, const int* in_sizes, int n_in,
                              void* d_out, int out_size) {
    const float* x     = (const float*)d_in[0];
    const float* Wq    = (const float*)d_in[1];
    const float* bq    = (const float*)d_in[2];
    const float* uq    = (const float*)d_in[3];
    const float* Wk    = (const float*)d_in[4];
    const float* bk    = (const float*)d_in[5];
    const float* uk    = (const float*)d_in[6];
    const float* Wv    = (const float*)d_in[7];
    const float* bv    = (const float*)d_in[8];
    const float* uv    = (const float*)d_in[9];
    const float* gamma = (const float*)d_in[10];
    float* out = (float*)d_out;

    static int inited = 0;
    if (!inited) {
        cudaFuncSetAttribute(proj_qk_mma, cudaFuncAttributeMaxDynamicSharedMemorySize, SMEM_GEMM);
        cudaFuncSetAttribute(proj_v_mma,  cudaFuncAttributeMaxDynamicSharedMemorySize, SMEM_GEMM);
        cudaFuncSetAttribute(gemm_qk_mma, cudaFuncAttributeMaxDynamicSharedMemorySize, SMEM_GEMM);
        cudaFuncSetAttribute(gemm_av_mma, cudaFuncAttributeMaxDynamicSharedMemorySize, SMEM_GEMM);
        inited = 1;
    }

    spectral_k<<<3, 512>>>(Wq, uq, Wk, uk, Wv, uv);
    build_w2k<<<(MR * CC + 255) / 256, 256>>>(Wq, bq, Wk, bk, Wv, bv);
    xsplit_k<<<dim3(NN / 32, CC / 32, BB), dim3(32, 8)>>>(x);
    proj_qk_mma<<<dim3(NN / 128, 1, BB), 256, SMEM_GEMM>>>();
    proj_v_mma<<<dim3(NN / 128, CC / 128, BB), 256, SMEM_GEMM>>>();
    gemm_qk_mma<<<dim3(NN / 128, NN / 128, BB), 256, SMEM_GEMM>>>();
    colsum_tc<<<(BB * NN) / 8, 256>>>();
    gemm_av_mma<<<dim3(NN / 128, CC / 128, BB), 256, SMEM_GEMM>>>(x, gamma, out);
}

// round 8
// speedup vs baseline: 2.2624x; 1.0221x over previous
#include <cuda_runtime.h>
#include <cuda_bf16.h>
#include <cstdint>

#define BB 32
#define CC 512
#define NN 1024
#define CQ 64
#define MR 640

// ---------------- scratch (device globals; no cudaMalloc) ----------------
__device__ float g_scale[3];
__device__ float g_bcat[MR];
__device__ __align__(16) __nv_bfloat16 g_w2h[MR * CC];
__device__ __align__(16) __nv_bfloat16 g_w2l[MR * CC];
__device__ __align__(16) __nv_bfloat16 g_xTh[(size_t)BB * NN * CC];
__device__ __align__(16) __nv_bfloat16 g_xTl[(size_t)BB * NN * CC];
__device__ __align__(16) __nv_bfloat16 g_qTh[(size_t)BB * NN * CQ];
__device__ __align__(16) __nv_bfloat16 g_qTl[(size_t)BB * NN * CQ];
__device__ __align__(16) __nv_bfloat16 g_kTh[(size_t)BB * NN * CQ];
__device__ __align__(16) __nv_bfloat16 g_kTl[(size_t)BB * NN * CQ];
__device__ __align__(16) __nv_bfloat16 g_vh [(size_t)BB * CC * NN];
__device__ __align__(16) __nv_bfloat16 g_vl [(size_t)BB * CC * NN];
__device__ __align__(16) __nv_bfloat16 g_pTh[(size_t)BB * NN * NN];
__device__ __align__(16) __nv_bfloat16 g_pTl[(size_t)BB * NN * NN];
__device__ float g_csum[BB * NN];
__device__ float g_cinv[BB * NN];

// ---------------- helpers ----------------
__device__ __forceinline__ uint32_t smem_u32(const void* p) {
    uint32_t a;
    asm("{ .reg .u64 t; cvta.to.shared.u64 t, %1; cvt.u32.u64 %0, t; }" : "=r"(a) : "l"(p));
    return a;
}
__device__ __forceinline__ void cp16(uint32_t s, const void* g) {
    asm volatile("cp.async.cg.shared.global [%0], [%1], 16;" :: "r"(s), "l"(g));
}
__device__ __forceinline__ void cp_commit() { asm volatile("cp.async.commit_group;" ::: "memory"); }
__device__ __forceinline__ void cp_wait1()  { asm volatile("cp.async.wait_group 1;" ::: "memory"); }
__device__ __forceinline__ void cp_wait0()  { asm volatile("cp.async.wait_group 0;" ::: "memory"); }

__device__ __forceinline__ void mma16816(float* c, uint32_t a0, uint32_t a1, uint32_t a2, uint32_t a3,
                                         uint32_t b0, uint32_t b1) {
    asm volatile(
        "mma.sync.aligned.m16n8k16.row.col.f32.bf16.bf16.f32 "
        "{%0,%1,%2,%3}, {%4,%5,%6,%7}, {%8,%9}, {%0,%1,%2,%3};"
        : "+f"(c[0]), "+f"(c[1]), "+f"(c[2]), "+f"(c[3])
        : "r"(a0), "r"(a1), "r"(a2), "r"(a3), "r"(b0), "r"(b1));
}

__device__ __forceinline__ void split2(float f, __nv_bfloat16& h, __nv_bfloat16& l) {
    h = __float2bfloat16(f);
    l = __float2bfloat16(f - __bfloat162float(h));
}
__device__ __forceinline__ uint32_t packbf(__nv_bfloat16 a, __nv_bfloat16 b) {
    __nv_bfloat162 t(a, b);
    return *reinterpret_cast<uint32_t*>(&t);
}

// smem geometry: per stage 4 arrays (Ah,Al,Bh,Bl), each 128 rows x 32 bf16
// stored with stride 40 elems (80 B) -> conflict-free fragment loads.
#define ARR_B   10240u
#define STAGE_B 40960u
#define SMEM_GEMM (2 * STAGE_B)          // 81920 B

// Issue one K-chunk (32 elems) of all 4 operand arrays into `stage` via cp.async.
__device__ __forceinline__ void issue_chunk(uint32_t su, int stage,
        const __nv_bfloat16* Ah, const __nv_bfloat16* Al, int lda,
        const __nv_bfloat16* Bh, const __nv_bfloat16* Bl, int ldb,
        int koff, int tid) {
    const __nv_bfloat16* ps[4] = { Ah, Al, Bh, Bl };
    #pragma unroll
    for (int a = 0; a < 4; a++) {
        int ld = (a < 2) ? lda : ldb;
        uint32_t sb = su + (uint32_t)stage * STAGE_B + (uint32_t)a * ARR_B;
        #pragma unroll
        for (int i = 0; i < 2; i++) {
            int idx = tid + 256 * i;
            int row = idx >> 2, seg = idx & 3;
            cp16(sb + (uint32_t)(row * 80 + seg * 16),
                 ps[a] + (size_t)row * ld + koff + seg * 8);
        }
    }
    cp_commit();
}

// One K-chunk of MMAs (2 ksteps x 4x4 tiles x 3 passes).
__device__ __forceinline__ void compute_chunk(const char* sm, int stage,
        int wm, int wn, int lane, float acc[4][4][4]) {
    int g = lane >> 2, t = lane & 3;
    const char* A0 = sm + stage * STAGE_B + (wm * 64 + g) * 80 + t * 4;
    const char* B0 = sm + stage * STAGE_B + 2 * ARR_B + (wn * 32 + g) * 80 + t * 4;
    #pragma unroll
    for (int kk = 0; kk < 2; kk++) {
        int kb = kk * 32;
        uint32_t ah[4][4], al[4][4], bh[4][2], bl[4][2];
        #pragma unroll
        for (int mt = 0; mt < 4; mt++) {
            const char* p = A0 + mt * 1280 + kb;
            ah[mt][0] = *(const uint32_t*)(p);
            ah[mt][1] = *(const uint32_t*)(p + 640);
            ah[mt][2] = *(const uint32_t*)(p + 16);
            ah[mt][3] = *(const uint32_t*)(p + 656);
            const char* q = p + ARR_B;
            al[mt][0] = *(const uint32_t*)(q);
            al[mt][1] = *(const uint32_t*)(q + 640);
            al[mt][2] = *(const uint32_t*)(q + 16);
            al[mt][3] = *(const uint32_t*)(q + 656);
        }
        #pragma unroll
        for (int nt = 0; nt < 4; nt++) {
            const char* p = B0 + nt * 640 + kb;
            bh[nt][0] = *(const uint32_t*)(p);
            bh[nt][1] = *(const uint32_t*)(p + 16);
            const char* q = p + ARR_B;
            bl[nt][0] = *(const uint32_t*)(q);
            bl[nt][1] = *(const uint32_t*)(q + 16);
        }
        #pragma unroll
        for (int mt = 0; mt < 4; mt++)
            #pragma unroll
            for (int nt = 0; nt < 4; nt++) {
                mma16816(acc[mt][nt], ah[mt][0], ah[mt][1], ah[mt][2], ah[mt][3], bh[nt][0], bh[nt][1]);
                mma16816(acc[mt][nt], al[mt][0], al[mt][1], al[mt][2], al[mt][3], bh[nt][0], bh[nt][1]);
                mma16816(acc[mt][nt], ah[mt][0], ah[mt][1], ah[mt][2], ah[mt][3], bl[nt][0], bl[nt][1]);
            }
    }
}

// Full double-buffered mainloop. acc indexed [mt][nt][4].
__device__ __forceinline__ void run_gemm(char* sm, uint32_t su,
        const __nv_bfloat16* Ah, const __nv_bfloat16* Al, int lda,
        const __nv_bfloat16* Bh, const __nv_bfloat16* Bl, int ldb,
        int nch, float acc[4][4][4]) {
    int tid = threadIdx.x, lane = tid & 31, wid = tid >> 5;
    int wm = wid >> 2, wn = wid & 3;
    #pragma unroll
    for (int i = 0; i < 4; i++)
        #pragma unroll
        for (int j = 0; j < 4; j++)
            #pragma unroll
            for (int e = 0; e < 4; e++) acc[i][j][e] = 0.f;

    issue_chunk(su, 0, Ah, Al, lda, Bh, Bl, ldb, 0, tid);
    issue_chunk(su, 1, Ah, Al, lda, Bh, Bl, ldb, 32, tid);
    for (int ch = 0; ch < nch; ch++) {
        if (ch == nch - 1) cp_wait0(); else cp_wait1();
        __syncthreads();
        compute_chunk(sm, ch & 1, wm, wn, lane, acc);
        __syncthreads();
        if (ch + 2 < nch)
            issue_chunk(su, ch & 1, Ah, Al, lda, Bh, Bl, ldb, (ch + 2) * 32, tid);
    }
}

// Stage one 64-row half of the 128x128 fp32 result into smem (stride 132).
__device__ __forceinline__ void stage_half(float* fb, int h, float acc[4][4][4]) {
    int tid = threadIdx.x, lane = tid & 31, wid = tid >> 5;
    int wm = wid >> 2, wn = wid & 3;
    if (wm != h) return;
    int g = lane >> 2, t = lane & 3;
    #pragma unroll
    for (int mt = 0; mt < 4; mt++)
        #pragma unroll
        for (int nt = 0; nt < 4; nt++) {
            float* p = fb + (mt * 16 + g) * 132 + wn * 32 + nt * 8 + 2 * t;
            p[0] = acc[mt][nt][0]; p[1] = acc[mt][nt][1];
            p[8 * 132] = acc[mt][nt][2]; p[8 * 132 + 1] = acc[mt][nt][3];
        }
}

// =================================================================
// Spectral norm (fp32)
// =================================================================
__global__ void spectral_k(const float* __restrict__ Wq, const float* __restrict__ uq,
                           const float* __restrict__ Wk, const float* __restrict__ uk,
                           const float* __restrict__ Wv, const float* __restrict__ uv) {
    const float* W; const float* u; int out;
    if (blockIdx.x == 0)      { W = Wq; u = uq; out = CQ; }
    else if (blockIdx.x == 1) { W = Wk; u = uk; out = CQ; }
    else                      { W = Wv; u = uv; out = CC; }
    const int in = CC;
    __shared__ float sv[CC];
    __shared__ float st[CC];
    __shared__ float red[16];
    int tid = threadIdx.x, lane = tid & 31, w = tid >> 5;

    float acc = 0.f;
    for (int i = 0; i < out; i++) acc += W[i * in + tid] * u[i];
    sv[tid] = acc;

    float s = acc * acc;
    #pragma unroll
    for (int o = 16; o; o >>= 1) s += __shfl_xor_sync(0xffffffffu, s, o);
    if (lane == 0) red[w] = s;
    __syncthreads();
    if (tid < 16) {
        float r = red[tid];
        #pragma unroll
        for (int o = 8; o; o >>= 1) r += __shfl_xor_sync(0xffffu, r, o);
        if (tid == 0) red[0] = r;
    }
    __syncthreads();
    float inv = rsqrtf(red[0]);
    __syncthreads();

    for (int i = w; i < out; i += 16) {
        float a = 0.f;
        for (int j = lane; j < in; j += 32) a += W[i * in + j] * sv[j];
        #pragma unroll
        for (int o = 16; o; o >>= 1) a += __shfl_xor_sync(0xffffffffu, a, o);
        if (lane == 0) st[i] = a * inv;
    }
    __syncthreads();

    float q = (tid < out) ? st[tid] * st[tid] : 0.f;
    #pragma unroll
    for (int o = 16; o; o >>= 1) q += __shfl_xor_sync(0xffffffffu, q, o);
    if (lane == 0) red[w] = q;
    __syncthreads();
    if (tid == 0) {
        float r = 0.f;
        #pragma unroll
        for (int i = 0; i < 16; i++) r += red[i];
        g_scale[blockIdx.x] = rsqrtf(r);
    }
}

// =================================================================
// Scaled concatenated weights -> bf16 hi/lo + fp32 bias; also zero csum
// =================================================================
__global__ void build_w2k(const float* __restrict__ Wq, const float* __restrict__ bq,
                          const float* __restrict__ Wk, const float* __restrict__ bk,
                          const float* __restrict__ Wv, const float* __restrict__ bv) {
    int idx = blockIdx.x * blockDim.x + threadIdx.x;
    if (idx >= MR * CC) return;
    if (idx < BB * NN) g_csum[idx] = 0.f;
    int r = idx >> 9, c = idx & (CC - 1);
    float wv, sc;
    if (r < CQ)          { wv = Wq[r * CC + c];            sc = g_scale[0]; }
    else if (r < 2 * CQ) { wv = Wk[(r - CQ) * CC + c];     sc = g_scale[1]; }
    else                 { wv = Wv[(r - 2 * CQ) * CC + c]; sc = g_scale[2]; }
    __nv_bfloat16 h, l;
    split2(wv * sc, h, l);
    g_w2h[idx] = h; g_w2l[idx] = l;
    if (c == 0)
        g_bcat[r] = (r < CQ) ? bq[r] : (r < 2 * CQ ? bk[r - CQ] : bv[r - 2 * CQ]);
}

// =================================================================
// Transpose+split x: [b][c][n] fp32 -> xT hi/lo bf16 [b][n][c]
// =================================================================
__global__ void xsplit_k(const float* __restrict__ x) {
    __shared__ float t[32][33];
    int b = blockIdx.z, n0 = blockIdx.x * 32, c0 = blockIdx.y * 32;
    int tx = threadIdx.x, ty = threadIdx.y;   // 32 x 8
    const float* xb = x + (size_t)b * CC * NN;
    #pragma unroll
    for (int j = 0; j < 4; j++)
        t[ty + 8 * j][tx] = xb[(size_t)(c0 + ty + 8 * j) * NN + n0 + tx];
    __syncthreads();
    #pragma unroll
    for (int j = 0; j < 4; j++) {
        int n = n0 + ty + 8 * j;
        __nv_bfloat16 h, l;
        split2(t[tx][ty + 8 * j], h, l);
        size_t o = ((size_t)b * NN + n) * CC + c0 + tx;
        g_xTh[o] = h; g_xTl[o] = l;
    }
}

// =================================================================
// proj_qk: D[n][r] = xT[n][:]·w[r][:] + b[r] -> qT/kT hi/lo [b][n][64]
// =================================================================
__global__ __launch_bounds__(256, 2)
void proj_qk_mma(void) {
    extern __shared__ __align__(16) char sm[];
    uint32_t su = smem_u32(sm);
    int b = blockIdx.z, n0 = blockIdx.x * 128;
    const __nv_bfloat16* Ah = g_xTh + ((size_t)b * NN + n0) * CC;
    const __nv_bfloat16* Al = g_xTl + ((size_t)b * NN + n0) * CC;
    float acc[4][4][4];
    run_gemm(sm, su, Ah, Al, CC, g_w2h, g_w2l, CC, CC / 32, acc);

    float* fb = (float*)sm;
    int tid = threadIdx.x, lane = tid & 31;
    for (int h = 0; h < 2; h++) {
        __syncthreads();
        stage_half(fb, h, acc);
        __syncthreads();
        #pragma unroll
        for (int j = 0; j < 8; j++) {
            int r = (tid >> 5) + j * 8;
            int n = n0 + h * 64 + r;
            int rr = lane * 4;
            const float* p = fb + r * 132 + rr;
            uint32_t hp[2], lp[2];
            #pragma unroll
            for (int e = 0; e < 2; e++) {
                float f0 = p[2 * e]     + g_bcat[rr + 2 * e];
                float f1 = p[2 * e + 1] + g_bcat[rr + 2 * e + 1];
                __nv_bfloat16 h0, l0, h1, l1;
                split2(f0, h0, l0); split2(f1, h1, l1);
                hp[e] = packbf(h0, h1); lp[e] = packbf(l0, l1);
            }
            size_t o;
            __nv_bfloat16 *dh, *dl;
            if (rr < 64) { o = ((size_t)b * NN + n) * CQ + rr;      dh = g_qTh; dl = g_qTl; }
            else         { o = ((size_t)b * NN + n) * CQ + rr - 64; dh = g_kTh; dl = g_kTl; }
            *reinterpret_cast<uint2*>(dh + o) = *reinterpret_cast<uint2*>(hp);
            *reinterpret_cast<uint2*>(dl + o) = *reinterpret_cast<uint2*>(lp);
        }
    }
}

// =================================================================
// proj_v: D[c][n] = wv[c][:]·xT[n][:] + bv[c] -> v hi/lo [b][c][n]
// =================================================================
__global__ __launch_bounds__(256, 2)
void proj_v_mma(void) {
    extern __shared__ __align__(16) char sm[];
    uint32_t su = smem_u32(sm);
    int b = blockIdx.z, n0 = blockIdx.x * 128, c0 = blockIdx.y * 128;
    const __nv_bfloat16* Ah = g_w2h + (size_t)(2 * CQ + c0) * CC;
    const __nv_bfloat16* Al = g_w2l + (size_t)(2 * CQ + c0) * CC;
    const __nv_bfloat16* Bh = g_xTh + ((size_t)b * NN + n0) * CC;
    const __nv_bfloat16* Bl = g_xTl + ((size_t)b * NN + n0) * CC;
    float acc[4][4][4];
    run_gemm(sm, su, Ah, Al, CC, Bh, Bl, CC, CC / 32, acc);

    float* fb = (float*)sm;
    int tid = threadIdx.x, lane = tid & 31;
    for (int h = 0; h < 2; h++) {
        __syncthreads();
        stage_half(fb, h, acc);
        __syncthreads();
        #pragma unroll
        for (int j = 0; j < 8; j++) {
            int r = (tid >> 5) + j * 8;
            int c = c0 + h * 64 + r;
            float bias = g_bcat[2 * CQ + c];
            const float* p = fb + r * 132 + lane * 4;
            uint32_t hp[2], lp[2];
            #pragma unroll
            for (int e = 0; e < 2; e++) {
                __nv_bfloat16 h0, l0, h1, l1;
                split2(p[2 * e] + bias, h0, l0);
                split2(p[2 * e + 1] + bias, h1, l1);
                hp[e] = packbf(h0, h1); lp[e] = packbf(l0, l1);
            }
            size_t o = ((size_t)b * CC + c) * NN + n0 + lane * 4;
            *reinterpret_cast<uint2*>(g_vh + o) = *reinterpret_cast<uint2*>(hp);
            *reinterpret_cast<uint2*>(g_vl + o) = *reinterpret_cast<uint2*>(lp);
        }
    }
}

// =================================================================
// QK: D[m][n] = kT[m][:]·qT[n][:];  pT = exp(D) hi/lo; csum += row sums
// =================================================================
__global__ __launch_bounds__(256, 2)
void gemm_qk_mma(void) {
    extern __shared__ __align__(16) char sm[];
    uint32_t su = smem_u32(sm);
    int b = blockIdx.z, m0 = blockIdx.y * 128, n0 = blockIdx.x * 128;
    const __nv_bfloat16* Ah = g_kTh + ((size_t)b * NN + m0) * CQ;
    const __nv_bfloat16* Al = g_kTl + ((size_t)b * NN + m0) * CQ;
    const __nv_bfloat16* Bh = g_qTh + ((size_t)b * NN + n0) * CQ;
    const __nv_bfloat16* Bl = g_qTl + ((size_t)b * NN + n0) * CQ;
    float acc[4][4][4];
    run_gemm(sm, su, Ah, Al, CQ, Bh, Bl, CQ, CQ / 32, acc);

    float* fb = (float*)sm;
    int tid = threadIdx.x, lane = tid & 31;
    for (int h = 0; h < 2; h++) {
        __syncthreads();
        stage_half(fb, h, acc);
        __syncthreads();
        #pragma unroll
        for (int j = 0; j < 8; j++) {
            int r = (tid >> 5) + j * 8;       // whole warp shares row r
            int m = m0 + h * 64 + r;
            const float* p = fb + r * 132 + lane * 4;
            uint32_t hp[2], lp[2];
            float rs = 0.f;
            #pragma unroll
            for (int e = 0; e < 2; e++) {
                float f0 = __expf(p[2 * e]);
                float f1 = __expf(p[2 * e + 1]);
                rs += f0 + f1;
                __nv_bfloat16 h0, l0, h1, l1;
                split2(f0, h0, l0); split2(f1, h1, l1);
                hp[e] = packbf(h0, h1); lp[e] = packbf(l0, l1);
            }
            size_t o = ((size_t)b * NN + m) * NN + n0 + lane * 4;
            *reinterpret_cast<uint2*>(g_pTh + o) = *reinterpret_cast<uint2*>(hp);
            *reinterpret_cast<uint2*>(g_pTl + o) = *reinterpret_cast<uint2*>(lp);
            // warp-reduce the 128-col partial row sum, one atomic per warp-row
            #pragma unroll
            for (int of = 16; of; of >>= 1) rs += __shfl_xor_sync(0xffffffffu, rs, of);
            if (lane == 0) atomicAdd(&g_csum[b * NN + m], rs);
        }
    }
}

// =================================================================
// invert csum -> cinv
// =================================================================
__global__ void inv_k(void) {
    int i = blockIdx.x * blockDim.x + threadIdx.x;
    if (i < BB * NN) g_cinv[i] = 1.0f / g_csum[i];
}

// =================================================================
// AV: D[c][m] = v[c][:]·pT[m][:];  out = gamma*cinv[m]*D + x
// =================================================================
__global__ __launch_bounds__(256, 2)
void gemm_av_mma(const float* __restrict__ x, const float* __restrict__ gamma,
                 float* __restrict__ out) {
    extern __shared__ __align__(16) char sm[];
    uint32_t su = smem_u32(sm);
    int b = blockIdx.z, m0 = blockIdx.x * 128, c0 = blockIdx.y * 128;
    const __nv_bfloat16* Ah = g_vh  + ((size_t)b * CC + c0) * NN;
    const __nv_bfloat16* Al = g_vl  + ((size_t)b * CC + c0) * NN;
    const __nv_bfloat16* Bh = g_pTh + ((size_t)b * NN + m0) * NN;
    const __nv_bfloat16* Bl = g_pTl + ((size_t)b * NN + m0) * NN;
    float acc[4][4][4];
    run_gemm(sm, su, Ah, Al, NN, Bh, Bl, NN, NN / 32, acc);

    float* fb = (float*)sm;
    int tid = threadIdx.x, lane = tid & 31;
    float gm = *gamma;
    for (int h = 0; h < 2; h++) {
        __syncthreads();
        stage_half(fb, h, acc);
        __syncthreads();
        #pragma unroll
        for (int j = 0; j < 8; j++) {
            int r = (tid >> 5) + j * 8;
            int c = c0 + h * 64 + r;
            int m = m0 + lane * 4;
            float4 d = *reinterpret_cast<const float4*>(fb + r * 132 + lane * 4);
            float4 ci = *reinterpret_cast<const float4*>(g_cinv + b * NN + m);
            size_t o = ((size_t)b * CC + c) * NN + m;
            float4 xv = *reinterpret_cast<const float4*>(x + o);
            float4 ov;
            ov.x = gm * ci.x * d.x + xv.x;
            ov.y = gm * ci.y * d.y + xv.y;
            ov.z = gm * ci.z * d.z + xv.z;
            ov.w = gm * ci.w * d.w + xv.w;
            *reinterpret_cast<float4*>(out + o) = ov;
        }
    }
}

// =================================================================
extern "C" void kernel_launch(void* const* d_in, const int* in_sizes, int n_in,
                              void* d_out, int out_size) {
    const float* x     = (const float*)d_in[0];
    const float* Wq    = (const float*)d_in[1];
    const float* bq    = (const float*)d_in[2];
    const float* uq    = (const float*)d_in[3];
    const float* Wk    = (const float*)d_in[4];
    const float* bk    = (const float*)d_in[5];
    const float* uk    = (const float*)d_in[6];
    const float* Wv    = (const float*)d_in[7];
    const float* bv    = (const float*)d_in[8];
    const float* uv    = (const float*)d_in[9];
    const float* gamma = (const float*)d_in[10];
    float* out = (float*)d_out;

    static int inited = 0;
    if (!inited) {
        cudaFuncSetAttribute(proj_qk_mma, cudaFuncAttributeMaxDynamicSharedMemorySize, SMEM_GEMM);
        cudaFuncSetAttribute(proj_v_mma,  cudaFuncAttributeMaxDynamicSharedMemorySize, SMEM_GEMM);
        cudaFuncSetAttribute(gemm_qk_mma, cudaFuncAttributeMaxDynamicSharedMemorySize, SMEM_GEMM);
        cudaFuncSetAttribute(gemm_av_mma, cudaFuncAttributeMaxDynamicSharedMemorySize, SMEM_GEMM);
        inited = 1;
    }

    spectral_k<<<3, 512>>>(Wq, uq, Wk, uk, Wv, uv);
    build_w2k<<<(MR * CC + 255) / 256, 256>>>(Wq, bq, Wk, bk, Wv, bv);
    xsplit_k<<<dim3(NN / 32, CC / 32, BB), dim3(32, 8)>>>(x);
    proj_qk_mma<<<dim3(NN / 128, 1, BB), 256, SMEM_GEMM>>>();
    proj_v_mma<<<dim3(NN / 128, CC / 128, BB), 256, SMEM_GEMM>>>();
    gemm_qk_mma<<<dim3(NN / 128, NN / 128, BB), 256, SMEM_GEMM>>>();
    inv_k<<<(BB * NN + 255) / 256, 256>>>();
    gemm_av_mma<<<dim3(NN / 128, CC / 128, BB), 256, SMEM_GEMM>>>(x, gamma, out);
}

// round 9
// speedup vs baseline: 2.7166x; 1.2008x over previous
#include <cuda_runtime.h>
#include <cuda_bf16.h>
#include <cstdint>

#define BB 32
#define CC 512
#define NN 1024
#define CQ 64
#define MR 640

// ---------------- scratch (device globals; no cudaMalloc) ----------------
__device__ float g_scale[3];
__device__ float g_bcat[MR];
__device__ __align__(16) __nv_bfloat16 g_w2h[MR * CC];
__device__ __align__(16) __nv_bfloat16 g_w2l[MR * CC];
__device__ __align__(16) __nv_bfloat16 g_xTh[(size_t)BB * NN * CC];
__device__ __align__(16) __nv_bfloat16 g_xTl[(size_t)BB * NN * CC];
__device__ __align__(16) __nv_bfloat16 g_qTh[(size_t)BB * NN * CQ];
__device__ __align__(16) __nv_bfloat16 g_qTl[(size_t)BB * NN * CQ];
__device__ __align__(16) __nv_bfloat16 g_kTh[(size_t)BB * NN * CQ];
__device__ __align__(16) __nv_bfloat16 g_kTl[(size_t)BB * NN * CQ];
__device__ __align__(16) __nv_bfloat16 g_vh [(size_t)BB * CC * NN];
__device__ __align__(16) __nv_bfloat16 g_vl [(size_t)BB * CC * NN];
__device__ __align__(16) __nv_bfloat16 g_pTh[(size_t)BB * NN * NN];
__device__ float g_csum[BB * NN];
__device__ float g_cinv[BB * NN];

// ---------------- helpers ----------------
__device__ __forceinline__ uint32_t smem_u32(const void* p) {
    uint32_t a;
    asm("{ .reg .u64 t; cvta.to.shared.u64 t, %1; cvt.u32.u64 %0, t; }" : "=r"(a) : "l"(p));
    return a;
}
__device__ __forceinline__ void cp16(uint32_t s, const void* g) {
    asm volatile("cp.async.cg.shared.global [%0], [%1], 16;" :: "r"(s), "l"(g));
}
__device__ __forceinline__ void cp_commit() { asm volatile("cp.async.commit_group;" ::: "memory"); }
__device__ __forceinline__ void cp_wait1()  { asm volatile("cp.async.wait_group 1;" ::: "memory"); }
__device__ __forceinline__ void cp_wait0()  { asm volatile("cp.async.wait_group 0;" ::: "memory"); }

__device__ __forceinline__ void ldsm4(uint32_t r[4], uint32_t addr) {
    asm volatile("ldmatrix.sync.aligned.m8n8.x4.shared.b16 {%0,%1,%2,%3}, [%4];"
        : "=r"(r[0]), "=r"(r[1]), "=r"(r[2]), "=r"(r[3]) : "r"(addr));
}

__device__ __forceinline__ void mma16816(float* c, const uint32_t a[4], uint32_t b0, uint32_t b1) {
    asm volatile(
        "mma.sync.aligned.m16n8k16.row.col.f32.bf16.bf16.f32 "
        "{%0,%1,%2,%3}, {%4,%5,%6,%7}, {%8,%9}, {%0,%1,%2,%3};"
        : "+f"(c[0]), "+f"(c[1]), "+f"(c[2]), "+f"(c[3])
        : "r"(a[0]), "r"(a[1]), "r"(a[2]), "r"(a[3]), "r"(b0), "r"(b1));
}

__device__ __forceinline__ void split2(float f, __nv_bfloat16& h, __nv_bfloat16& l) {
    h = __float2bfloat16(f);
    l = __float2bfloat16(f - __bfloat162float(h));
}
__device__ __forceinline__ uint32_t packbf(__nv_bfloat16 a, __nv_bfloat16 b) {
    __nv_bfloat162 t(a, b);
    return *reinterpret_cast<uint32_t*>(&t);
}

// smem geometry: per stage 3 or 4 arrays (Ah,Al,Bh[,Bl]), each 128 rows x 32 bf16
// stored with stride 40 elems (80 B) -> conflict-free LDSM (banks r*20%32 distinct).
#define ARR_B   10240u
#define SMEM_G3 (2u * 4u * ARR_B)   // 81920: 3-pass kernels (Bl present)
#define SMEM_G2 (2u * 3u * ARR_B)   // 61440: AV (no Bl)

// Issue one K-chunk (32 elems) of operand arrays into `stage` via cp.async.
template<bool BL>
__device__ __forceinline__ void issue_chunk(uint32_t su, int stage,
        const __nv_bfloat16* Ah, const __nv_bfloat16* Al, int lda,
        const __nv_bfloat16* Bh, const __nv_bfloat16* Bl, int ldb,
        int koff, int tid) {
    const uint32_t STG = (BL ? 4u : 3u) * ARR_B;
    const __nv_bfloat16* ps[4] = { Ah, Al, Bh, Bl };
    const int NA = BL ? 4 : 3;
    #pragma unroll
    for (int a = 0; a < NA; a++) {
        int ld = (a < 2) ? lda : ldb;
        uint32_t sb = su + (uint32_t)stage * STG + (uint32_t)a * ARR_B;
        #pragma unroll
        for (int i = 0; i < 2; i++) {
            int idx = tid + 256 * i;
            int row = idx >> 2, seg = idx & 3;
            cp16(sb + (uint32_t)(row * 80 + seg * 16),
                 ps[a] + (size_t)row * ld + koff + seg * 8);
        }
    }
    cp_commit();
}

// One K-chunk of MMAs via ldmatrix.x4 (2 ksteps x 16 tiles x 2-or-3 passes).
template<bool BL>
__device__ __forceinline__ void compute_chunk(uint32_t su, int stage,
        int wm, int wn, int lane, float acc[4][4][4]) {
    const uint32_t STG = (BL ? 4u : 3u) * ARR_B;
    uint32_t sbase = su + (uint32_t)stage * STG;
    int j = lane >> 3, r7 = lane & 7;
    // A (row-major m16k16): j0:(m0-7,k0-7) j1:(m8-15,k0-7) j2:(m0-7,k8-15) j3:(m8-15,k8-15)
    uint32_t Abase = sbase + (uint32_t)((wm * 64 + (j & 1) * 8 + r7) * 80 + (j >> 1) * 16);
    // B ([n][k] rows): j0:(n0-7,k0-7) j1:(n0-7,k8-15) j2:(n8-15,k0-7) j3:(n8-15,k8-15)
    uint32_t Bbase = sbase + 2u * ARR_B + (uint32_t)((wn * 32 + (j >> 1) * 8 + r7) * 80 + (j & 1) * 16);
    #pragma unroll
    for (int kk = 0; kk < 2; kk++) {
        uint32_t ko = (uint32_t)(kk * 32);
        uint32_t ah[4][4], al[4][4], bh[2][4], bl[2][4];
        #pragma unroll
        for (int mt = 0; mt < 4; mt++) ldsm4(ah[mt], Abase + (uint32_t)(mt * 1280) + ko);
        #pragma unroll
        for (int mt = 0; mt < 4; mt++) ldsm4(al[mt], Abase + ARR_B + (uint32_t)(mt * 1280) + ko);
        #pragma unroll
        for (int np = 0; np < 2; np++) ldsm4(bh[np], Bbase + (uint32_t)(np * 1280) + ko);
        if (BL) {
            #pragma unroll
            for (int np = 0; np < 2; np++) ldsm4(bl[np], Bbase + ARR_B + (uint32_t)(np * 1280) + ko);
        }
        #pragma unroll
        for (int mt = 0; mt < 4; mt++)
            #pragma unroll
            for (int nt = 0; nt < 4; nt++) {
                int np = nt >> 1, o = (nt & 1) * 2;
                mma16816(acc[mt][nt], ah[mt], bh[np][o], bh[np][o + 1]);
                mma16816(acc[mt][nt], al[mt], bh[np][o], bh[np][o + 1]);
                if (BL) mma16816(acc[mt][nt], ah[mt], bl[np][o], bl[np][o + 1]);
            }
    }
}

// Full double-buffered mainloop. acc indexed [mt][nt][4].
template<bool BL>
__device__ __forceinline__ void run_gemm(uint32_t su,
        const __nv_bfloat16* Ah, const __nv_bfloat16* Al, int lda,
        const __nv_bfloat16* Bh, const __nv_bfloat16* Bl, int ldb,
        int nch, float acc[4][4][4]) {
    int tid = threadIdx.x, lane = tid & 31, wid = tid >> 5;
    int wm = wid >> 2, wn = wid & 3;
    #pragma unroll
    for (int i = 0; i < 4; i++)
        #pragma unroll
        for (int j = 0; j < 4; j++)
            #pragma unroll
            for (int e = 0; e < 4; e++) acc[i][j][e] = 0.f;

    issue_chunk<BL>(su, 0, Ah, Al, lda, Bh, Bl, ldb, 0, tid);
    issue_chunk<BL>(su, 1, Ah, Al, lda, Bh, Bl, ldb, 32, tid);
    for (int ch = 0; ch < nch; ch++) {
        if (ch == nch - 1) cp_wait0(); else cp_wait1();
        __syncthreads();
        compute_chunk<BL>(su, ch & 1, wm, wn, lane, acc);
        __syncthreads();
        if (ch + 2 < nch)
            issue_chunk<BL>(su, ch & 1, Ah, Al, lda, Bh, Bl, ldb, (ch + 2) * 32, tid);
    }
}

// Stage one 64-row half of the 128x128 fp32 result into smem (stride 132).
__device__ __forceinline__ void stage_half(float* fb, int h, float acc[4][4][4]) {
    int tid = threadIdx.x, lane = tid & 31, wid = tid >> 5;
    int wm = wid >> 2, wn = wid & 3;
    if (wm != h) return;
    int g = lane >> 2, t = lane & 3;
    #pragma unroll
    for (int mt = 0; mt < 4; mt++)
        #pragma unroll
        for (int nt = 0; nt < 4; nt++) {
            float* p = fb + (mt * 16 + g) * 132 + wn * 32 + nt * 8 + 2 * t;
            p[0] = acc[mt][nt][0]; p[1] = acc[mt][nt][1];
            p[8 * 132] = acc[mt][nt][2]; p[8 * 132 + 1] = acc[mt][nt][3];
        }
}

// =================================================================
// Spectral norm (fp32)
// =================================================================
__global__ void spectral_k(const float* __restrict__ Wq, const float* __restrict__ uq,
                           const float* __restrict__ Wk, const float* __restrict__ uk,
                           const float* __restrict__ Wv, const float* __restrict__ uv) {
    const float* W; const float* u; int out;
    if (blockIdx.x == 0)      { W = Wq; u = uq; out = CQ; }
    else if (blockIdx.x == 1) { W = Wk; u = uk; out = CQ; }
    else                      { W = Wv; u = uv; out = CC; }
    const int in = CC;
    __shared__ float sv[CC];
    __shared__ float st[CC];
    __shared__ float red[16];
    int tid = threadIdx.x, lane = tid & 31, w = tid >> 5;

    float acc = 0.f;
    for (int i = 0; i < out; i++) acc += W[i * in + tid] * u[i];
    sv[tid] = acc;

    float s = acc * acc;
    #pragma unroll
    for (int o = 16; o; o >>= 1) s += __shfl_xor_sync(0xffffffffu, s, o);
    if (lane == 0) red[w] = s;
    __syncthreads();
    if (tid < 16) {
        float r = red[tid];
        #pragma unroll
        for (int o = 8; o; o >>= 1) r += __shfl_xor_sync(0xffffu, r, o);
        if (tid == 0) red[0] = r;
    }
    __syncthreads();
    float inv = rsqrtf(red[0]);
    __syncthreads();

    for (int i = w; i < out; i += 16) {
        float a = 0.f;
        for (int j = lane; j < in; j += 32) a += W[i * in + j] * sv[j];
        #pragma unroll
        for (int o = 16; o; o >>= 1) a += __shfl_xor_sync(0xffffffffu, a, o);
        if (lane == 0) st[i] = a * inv;
    }
    __syncthreads();

    float q = (tid < out) ? st[tid] * st[tid] : 0.f;
    #pragma unroll
    for (int o = 16; o; o >>= 1) q += __shfl_xor_sync(0xffffffffu, q, o);
    if (lane == 0) red[w] = q;
    __syncthreads();
    if (tid == 0) {
        float r = 0.f;
        #pragma unroll
        for (int i = 0; i < 16; i++) r += red[i];
        g_scale[blockIdx.x] = rsqrtf(r);
    }
}

// =================================================================
// Scaled concatenated weights -> bf16 hi/lo + fp32 bias; also zero csum
// =================================================================
__global__ void build_w2k(const float* __restrict__ Wq, const float* __restrict__ bq,
                          const float* __restrict__ Wk, const float* __restrict__ bk,
                          const float* __restrict__ Wv, const float* __restrict__ bv) {
    int idx = blockIdx.x * blockDim.x + threadIdx.x;
    if (idx >= MR * CC) return;
    if (idx < BB * NN) g_csum[idx] = 0.f;
    int r = idx >> 9, c = idx & (CC - 1);
    float wv, sc;
    if (r < CQ)          { wv = Wq[r * CC + c];            sc = g_scale[0]; }
    else if (r < 2 * CQ) { wv = Wk[(r - CQ) * CC + c];     sc = g_scale[1]; }
    else                 { wv = Wv[(r - 2 * CQ) * CC + c]; sc = g_scale[2]; }
    __nv_bfloat16 h, l;
    split2(wv * sc, h, l);
    g_w2h[idx] = h; g_w2l[idx] = l;
    if (c == 0)
        g_bcat[r] = (r < CQ) ? bq[r] : (r < 2 * CQ ? bk[r - CQ] : bv[r - 2 * CQ]);
}

// =================================================================
// Transpose+split x: [b][c][n] fp32 -> xT hi/lo bf16 [b][n][c]
// =================================================================
__global__ void xsplit_k(const float* __restrict__ x) {
    __shared__ float t[32][33];
    int b = blockIdx.z, n0 = blockIdx.x * 32, c0 = blockIdx.y * 32;
    int tx = threadIdx.x, ty = threadIdx.y;   // 32 x 8
    const float* xb = x + (size_t)b * CC * NN;
    #pragma unroll
    for (int j = 0; j < 4; j++)
        t[ty + 8 * j][tx] = xb[(size_t)(c0 + ty + 8 * j) * NN + n0 + tx];
    __syncthreads();
    #pragma unroll
    for (int j = 0; j < 4; j++) {
        int n = n0 + ty + 8 * j;
        __nv_bfloat16 h, l;
        split2(t[tx][ty + 8 * j], h, l);
        size_t o = ((size_t)b * NN + n) * CC + c0 + tx;
        g_xTh[o] = h; g_xTl[o] = l;
    }
}

// =================================================================
// proj_qk: D[n][r] = xT[n][:]·w[r][:] + b[r] -> qT/kT hi/lo [b][n][64]
// =================================================================
__global__ __launch_bounds__(256, 2)
void proj_qk_mma(void) {
    extern __shared__ __align__(16) char sm[];
    uint32_t su = smem_u32(sm);
    int b = blockIdx.z, n0 = blockIdx.x * 128;
    const __nv_bfloat16* Ah = g_xTh + ((size_t)b * NN + n0) * CC;
    const __nv_bfloat16* Al = g_xTl + ((size_t)b * NN + n0) * CC;
    float acc[4][4][4];
    run_gemm<true>(su, Ah, Al, CC, g_w2h, g_w2l, CC, CC / 32, acc);

    float* fb = (float*)sm;
    int tid = threadIdx.x, lane = tid & 31;
    for (int h = 0; h < 2; h++) {
        __syncthreads();
        stage_half(fb, h, acc);
        __syncthreads();
        #pragma unroll
        for (int j = 0; j < 8; j++) {
            int r = (tid >> 5) + j * 8;
            int n = n0 + h * 64 + r;
            int rr = lane * 4;
            const float* p = fb + r * 132 + rr;
            uint32_t hp[2], lp[2];
            #pragma unroll
            for (int e = 0; e < 2; e++) {
                float f0 = p[2 * e]     + g_bcat[rr + 2 * e];
                float f1 = p[2 * e + 1] + g_bcat[rr + 2 * e + 1];
                __nv_bfloat16 h0, l0, h1, l1;
                split2(f0, h0, l0); split2(f1, h1, l1);
                hp[e] = packbf(h0, h1); lp[e] = packbf(l0, l1);
            }
            size_t o;
            __nv_bfloat16 *dh, *dl;
            if (rr < 64) { o = ((size_t)b * NN + n) * CQ + rr;      dh = g_qTh; dl = g_qTl; }
            else         { o = ((size_t)b * NN + n) * CQ + rr - 64; dh = g_kTh; dl = g_kTl; }
            *reinterpret_cast<uint2*>(dh + o) = *reinterpret_cast<uint2*>(hp);
            *reinterpret_cast<uint2*>(dl + o) = *reinterpret_cast<uint2*>(lp);
        }
    }
}

// =================================================================
// proj_v: D[c][n] = wv[c][:]·xT[n][:] + bv[c] -> v hi/lo [b][c][n]
// =================================================================
__global__ __launch_bounds__(256, 2)
void proj_v_mma(void) {
    extern __shared__ __align__(16) char sm[];
    uint32_t su = smem_u32(sm);
    int b = blockIdx.z, n0 = blockIdx.x * 128, c0 = blockIdx.y * 128;
    const __nv_bfloat16* Ah = g_w2h + (size_t)(2 * CQ + c0) * CC;
    const __nv_bfloat16* Al = g_w2l + (size_t)(2 * CQ + c0) * CC;
    const __nv_bfloat16* Bh = g_xTh + ((size_t)b * NN + n0) * CC;
    const __nv_bfloat16* Bl = g_xTl + ((size_t)b * NN + n0) * CC;
    float acc[4][4][4];
    run_gemm<true>(su, Ah, Al, CC, Bh, Bl, CC, CC / 32, acc);

    float* fb = (float*)sm;
    int tid = threadIdx.x, lane = tid & 31;
    for (int h = 0; h < 2; h++) {
        __syncthreads();
        stage_half(fb, h, acc);
        __syncthreads();
        #pragma unroll
        for (int j = 0; j < 8; j++) {
            int r = (tid >> 5) + j * 8;
            int c = c0 + h * 64 + r;
            float bias = g_bcat[2 * CQ + c];
            const float* p = fb + r * 132 + lane * 4;
            uint32_t hp[2], lp[2];
            #pragma unroll
            for (int e = 0; e < 2; e++) {
                __nv_bfloat16 h0, l0, h1, l1;
                split2(p[2 * e] + bias, h0, l0);
                split2(p[2 * e + 1] + bias, h1, l1);
                hp[e] = packbf(h0, h1); lp[e] = packbf(l0, l1);
            }
            size_t o = ((size_t)b * CC + c) * NN + n0 + lane * 4;
            *reinterpret_cast<uint2*>(g_vh + o) = *reinterpret_cast<uint2*>(hp);
            *reinterpret_cast<uint2*>(g_vl + o) = *reinterpret_cast<uint2*>(lp);
        }
    }
}

// =================================================================
// QK: D[m][n] = kT[m][:]·qT[n][:];  pT = bf16(exp(D)); csum += rounded sums
// =================================================================
__global__ __launch_bounds__(256, 2)
void gemm_qk_mma(void) {
    extern __shared__ __align__(16) char sm[];
    uint32_t su = smem_u32(sm);
    int b = blockIdx.z, m0 = blockIdx.y * 128, n0 = blockIdx.x * 128;
    const __nv_bfloat16* Ah = g_kTh + ((size_t)b * NN + m0) * CQ;
    const __nv_bfloat16* Al = g_kTl + ((size_t)b * NN + m0) * CQ;
    const __nv_bfloat16* Bh = g_qTh + ((size_t)b * NN + n0) * CQ;
    const __nv_bfloat16* Bl = g_qTl + ((size_t)b * NN + n0) * CQ;
    float acc[4][4][4];
    run_gemm<true>(su, Ah, Al, CQ, Bh, Bl, CQ, CQ / 32, acc);

    float* fb = (float*)sm;
    int tid = threadIdx.x, lane = tid & 31;
    for (int h = 0; h < 2; h++) {
        __syncthreads();
        stage_half(fb, h, acc);
        __syncthreads();
        #pragma unroll
        for (int j = 0; j < 8; j++) {
            int r = (tid >> 5) + j * 8;       // whole warp shares row r
            int m = m0 + h * 64 + r;
            const float* p = fb + r * 132 + lane * 4;
            uint32_t hp[2];
            float rs = 0.f;
            #pragma unroll
            for (int e = 0; e < 2; e++) {
                __nv_bfloat16 h0 = __float2bfloat16(__expf(p[2 * e]));
                __nv_bfloat16 h1 = __float2bfloat16(__expf(p[2 * e + 1]));
                // sum the ROUNDED values so AV's normalization matches exactly
                rs += __bfloat162float(h0) + __bfloat162float(h1);
                hp[e] = packbf(h0, h1);
            }
            size_t o = ((size_t)b * NN + m) * NN + n0 + lane * 4;
            *reinterpret_cast<uint2*>(g_pTh + o) = *reinterpret_cast<uint2*>(hp);
            #pragma unroll
            for (int of = 16; of; of >>= 1) rs += __shfl_xor_sync(0xffffffffu, rs, of);
            if (lane == 0) atomicAdd(&g_csum[b * NN + m], rs);
        }
    }
}

// =================================================================
// invert csum -> cinv
// =================================================================
__global__ void inv_k(void) {
    int i = blockIdx.x * blockDim.x + threadIdx.x;
    if (i < BB * NN) g_cinv[i] = 1.0f / g_csum[i];
}

// =================================================================
// AV (2-pass, B = p hi only): D[c][m] = v[c][:]·pT[m][:]
// out = gamma*cinv[m]*D + x
// =================================================================
__global__ __launch_bounds__(256, 2)
void gemm_av_mma(const float* __restrict__ x, const float* __restrict__ gamma,
                 float* __restrict__ out) {
    extern __shared__ __align__(16) char sm[];
    uint32_t su = smem_u32(sm);
    int b = blockIdx.z, m0 = blockIdx.x * 128, c0 = blockIdx.y * 128;
    const __nv_bfloat16* Ah = g_vh  + ((size_t)b * CC + c0) * NN;
    const __nv_bfloat16* Al = g_vl  + ((size_t)b * CC + c0) * NN;
    const __nv_bfloat16* Bh = g_pTh + ((size_t)b * NN + m0) * NN;
    float acc[4][4][4];
    run_gemm<false>(su, Ah, Al, NN, Bh, (const __nv_bfloat16*)0, NN, NN / 32, acc);

    float* fb = (float*)sm;
    int tid = threadIdx.x, lane = tid & 31;
    float gm = *gamma;
    for (int h = 0; h < 2; h++) {
        __syncthreads();
        stage_half(fb, h, acc);
        __syncthreads();
        #pragma unroll
        for (int j = 0; j < 8; j++) {
            int r = (tid >> 5) + j * 8;
            int c = c0 + h * 64 + r;
            int m = m0 + lane * 4;
            float4 d = *reinterpret_cast<const float4*>(fb + r * 132 + lane * 4);
            float4 ci = *reinterpret_cast<const float4*>(g_cinv + b * NN + m);
            size_t o = ((size_t)b * CC + c) * NN + m;
            float4 xv = *reinterpret_cast<const float4*>(x + o);
            float4 ov;
            ov.x = gm * ci.x * d.x + xv.x;
            ov.y = gm * ci.y * d.y + xv.y;
            ov.z = gm * ci.z * d.z + xv.z;
            ov.w = gm * ci.w * d.w + xv.w;
            *reinterpret_cast<float4*>(out + o) = ov;
        }
    }
}

// =================================================================
extern "C" void kernel_launch(void* const* d_in, const int* in_sizes, int n_in,
                              void* d_out, int out_size) {
    const float* x     = (const float*)d_in[0];
    const float* Wq    = (const float*)d_in[1];
    const float* bq    = (const float*)d_in[2];
    const float* uq    = (const float*)d_in[3];
    const float* Wk    = (const float*)d_in[4];
    const float* bk    = (const float*)d_in[5];
    const float* uk    = (const float*)d_in[6];
    const float* Wv    = (const float*)d_in[7];
    const float* bv    = (const float*)d_in[8];
    const float* uv    = (const float*)d_in[9];
    const float* gamma = (const float*)d_in[10];
    float* out = (float*)d_out;

    static int inited = 0;
    if (!inited) {
        cudaFuncSetAttribute(proj_qk_mma, cudaFuncAttributeMaxDynamicSharedMemorySize, SMEM_G3);
        cudaFuncSetAttribute(proj_v_mma,  cudaFuncAttributeMaxDynamicSharedMemorySize, SMEM_G3);
        cudaFuncSetAttribute(gemm_qk_mma, cudaFuncAttributeMaxDynamicSharedMemorySize, SMEM_G3);
        cudaFuncSetAttribute(gemm_av_mma, cudaFuncAttributeMaxDynamicSharedMemorySize, SMEM_G2);
        inited = 1;
    }

    spectral_k<<<3, 512>>>(Wq, uq, Wk, uk, Wv, uv);
    build_w2k<<<(MR * CC + 255) / 256, 256>>>(Wq, bq, Wk, bk, Wv, bv);
    xsplit_k<<<dim3(NN / 32, CC / 32, BB), dim3(32, 8)>>>(x);
    proj_qk_mma<<<dim3(NN / 128, 1, BB), 256, SMEM_G3>>>();
    proj_v_mma<<<dim3(NN / 128, CC / 128, BB), 256, SMEM_G3>>>();
    gemm_qk_mma<<<dim3(NN / 128, NN / 128, BB), 256, SMEM_G3>>>();
    inv_k<<<(BB * NN + 255) / 256, 256>>>();
    gemm_av_mma<<<dim3(NN / 128, CC / 128, BB), 256, SMEM_G2>>>(x, gamma, out);
}